// round 8
// baseline (speedup 1.0000x reference)
#include <cuda_runtime.h>
#include <cuda_bf16.h>
#include <math.h>
#include <stdint.h>

#define DDIM  128
#define MC    128          // rows per CTA
#define NB    128          // centers per B tile
#define NTILE 8            // K / NB
#define KCENT 1024
#define EPSF  1e-12f
#define THREADS 512

// ---------------- device scratch (no allocations allowed) -------------------
__device__ __nv_bfloat16 g_cbf[KCENT * DDIM];   // normalized centers, bf16
__device__ double g_sum;

// ---------------- helpers ---------------------------------------------------
__device__ __forceinline__ uint32_t smem_u32(const void* p) {
    uint32_t a;
    asm("{ .reg .u64 t; cvta.to.shared.u64 t, %1; cvt.u32.u64 %0, t; }"
        : "=r"(a) : "l"(p));
    return a;
}
__device__ __forceinline__ void cpa16(uint32_t dst, const void* src) {
    asm volatile("cp.async.cg.shared.global [%0], [%1], 16;"
                 :: "r"(dst), "l"(src));
}
__device__ __forceinline__ void cpa_commit() {
    asm volatile("cp.async.commit_group;" ::: "memory");
}
__device__ __forceinline__ void cpa_wait0() {
    asm volatile("cp.async.wait_group 0;" ::: "memory");
}
__device__ __forceinline__ void ldsm_x4(uint32_t* r, uint32_t addr) {
    asm volatile("ldmatrix.sync.aligned.m8n8.x4.shared.b16 {%0,%1,%2,%3}, [%4];"
                 : "=r"(r[0]), "=r"(r[1]), "=r"(r[2]), "=r"(r[3]) : "r"(addr));
}
__device__ __forceinline__ void mma16816(float* d, const uint32_t* a,
                                         const uint32_t* b) {
    asm volatile(
        "mma.sync.aligned.m16n8k16.row.col.f32.bf16.bf16.f32 "
        "{%0,%1,%2,%3}, {%4,%5,%6,%7}, {%8,%9}, {%0,%1,%2,%3};"
        : "+f"(d[0]), "+f"(d[1]), "+f"(d[2]), "+f"(d[3])
        : "r"(a[0]), "r"(a[1]), "r"(a[2]), "r"(a[3]), "r"(b[0]), "r"(b[1]));
}
__device__ __forceinline__ uint32_t pack_bf2(float a, float b) {
    __nv_bfloat16 ha = __float2bfloat16(a);
    __nv_bfloat16 hb = __float2bfloat16(b);
    return (uint32_t)__bfloat16_as_ushort(ha)
         | ((uint32_t)__bfloat16_as_ushort(hb) << 16);
}
// row-major bf16 tile, 256B rows (16 x 16B chunks), XOR-8 swizzle
__device__ __forceinline__ uint32_t swz(uint32_t row, uint32_t chunk) {
    return row * 256u + ((chunk ^ (row & 7u)) << 4);
}

// ---------------------------------------------------------------------------
// Kernel A: normalize centers -> bf16 row-major; zero accumulator.
// ---------------------------------------------------------------------------
__global__ void prep_centers_kernel(const float* __restrict__ centers) {
    int k = blockIdx.x;
    int t = threadIdx.x;

    float v = centers[(size_t)k * DDIM + t];
    float s = v * v;
    #pragma unroll
    for (int o = 16; o; o >>= 1) s += __shfl_xor_sync(0xffffffffu, s, o);

    __shared__ float ws[4];
    __shared__ float n2s;
    if ((t & 31) == 0) ws[t >> 5] = s;
    __syncthreads();
    if (t == 0) {
        n2s = ws[0] + ws[1] + ws[2] + ws[3];
        if (k == 0) g_sum = 0.0;
    }
    __syncthreads();

    float ri = 1.0f / fmaxf(sqrtf(n2s), EPSF);
    g_cbf[(size_t)k * DDIM + t] = __float2bfloat16(v * ri);
}

// ---------------------------------------------------------------------------
// Kernel B: bf16 mma.sync GEMM (sims) + fused argmax + exact fp32 loss.
// 512 threads, 128 rows/CTA. Warp tile 16(m) x 64(n); warps 8(m) x 2(n).
// ---------------------------------------------------------------------------
__global__ void __launch_bounds__(THREADS, 1) cluster_main_kernel(
    const float* __restrict__ features,
    const float* __restrict__ centers, int N)
{
    extern __shared__ char dsm[];
    // layout: A (32KB) | B[2] (64KB) | s_ri (512B) | s_best (512B) | spart
    const uint32_t Ab = smem_u32(dsm);
    const uint32_t Bb = Ab + 32768u;
    float* s_ri   = (float*)(dsm + 98304);
    int*   s_best = (int*)  (dsm + 98304 + 512);
    float* spart  = (float*)(dsm + 98304 + 1024);

    const int tid  = threadIdx.x;
    const int lane = tid & 31;
    const int w    = tid >> 5;          // 0..15
    const int row0 = blockIdx.x * MC;

    // ---- kick off B tile 0 load ----
    {
        const char* src = (const char*)g_cbf;
        #pragma unroll
        for (int j = tid; j < 2048; j += THREADS) {
            int n = j >> 4, c = j & 15;
            cpa16(Bb + swz(n, c), src + n * 256 + c * 16);
        }
        cpa_commit();
    }

    // ---- phase 1: load 128 feature rows, normalize, bf16 -> smem A ----
    #pragma unroll 4
    for (int i = 0; i < 8; ++i) {
        int r = 8 * w + i;
        float4 v = *(const float4*)(features + (size_t)(row0 + r) * DDIM
                                    + 4 * lane);
        float s = v.x * v.x + v.y * v.y + v.z * v.z + v.w * v.w;
        #pragma unroll
        for (int o = 16; o; o >>= 1) s += __shfl_xor_sync(0xffffffffu, s, o);
        float ri = 1.0f / fmaxf(sqrtf(s), EPSF);
        if (lane == 0) s_ri[r] = ri;
        uint32_t p0 = pack_bf2(v.x * ri, v.y * ri);
        uint32_t p1 = pack_bf2(v.z * ri, v.w * ri);
        uint32_t addr = Ab + swz(r, lane >> 1) + (lane & 1) * 8;
        asm volatile("st.shared.v2.b32 [%0], {%1,%2};"
                     :: "r"(addr), "r"(p0), "r"(p1));
    }
    __syncthreads();

    // ---- warp tiling: 8(m) x 2(n) warps, warp tile 16 x 64 ----
    const int wm = w & 7, wn = w >> 3;
    const int rb = 16 * wm;          // warp row base
    const int nb0 = 64 * wn;         // warp col base within tile

    float best_v[2];
    int   best_i[2];
    #pragma unroll
    for (int s = 0; s < 2; ++s) { best_v[s] = -INFINITY; best_i[s] = 0; }

    #pragma unroll 1
    for (int t = 0; t < NTILE; ++t) {
        cpa_wait0();
        __syncthreads();
        const uint32_t Bt = Bb + (uint32_t)(t & 1) * 32768u;

        if (t < NTILE - 1) {   // prefetch next tile into other buffer
            const char* src = (const char*)(g_cbf + (size_t)(t + 1) * NB * DDIM);
            uint32_t dst = Bb + (uint32_t)((t + 1) & 1) * 32768u;
            #pragma unroll
            for (int j = tid; j < 2048; j += THREADS) {
                int n = j >> 4, c = j & 15;
                cpa16(dst + swz(n, c), src + n * 256 + c * 16);
            }
            cpa_commit();
        }

        float acc[8][4];
        #pragma unroll
        for (int b = 0; b < 8; ++b)
            #pragma unroll
            for (int e = 0; e < 4; ++e) acc[b][e] = 0.0f;

        #pragma unroll
        for (int ks = 0; ks < 8; ++ks) {
            uint32_t a0[4];
            {
                int row = rb + (lane & 15);
                int ch  = 2 * ks + (lane >> 4);
                ldsm_x4(a0, Ab + swz(row, ch));
            }
            uint32_t bfr[8][2];
            #pragma unroll
            for (int g = 0; g < 4; ++g) {
                int n  = nb0 + 16 * g + (lane & 7) + ((lane >> 4) << 3);
                int ch = 2 * ks + ((lane >> 3) & 1);
                uint32_t r4[4];
                ldsm_x4(r4, Bt + swz(n, ch));
                bfr[2 * g][0] = r4[0]; bfr[2 * g][1] = r4[1];
                bfr[2 * g + 1][0] = r4[2]; bfr[2 * g + 1][1] = r4[3];
            }
            #pragma unroll
            for (int nt = 0; nt < 8; ++nt) {
                mma16816(acc[nt], a0, bfr[nt]);
            }
        }
        __syncthreads();   // all warps done reading Bt before it is refilled

        // fold argmax: slot rh; rows rb + (lane>>2) + 8*rh
        const int kbase = t * NB + nb0 + 2 * (lane & 3);
        #pragma unroll
        for (int rh = 0; rh < 2; ++rh) {
            #pragma unroll
            for (int nt = 0; nt < 8; ++nt) {
                float v0 = acc[nt][2 * rh];
                float v1 = acc[nt][2 * rh + 1];
                int   i0 = kbase + 8 * nt;
                if (v0 > best_v[rh]) { best_v[rh] = v0; best_i[rh] = i0; }
                if (v1 > best_v[rh]) { best_v[rh] = v1; best_i[rh] = i0 + 1; }
            }
        }
    }

    // ---- reduce argmax over the 4 lanes of each quad ----
    #pragma unroll
    for (int off = 1; off < 4; off <<= 1) {
        #pragma unroll
        for (int s = 0; s < 2; ++s) {
            float ov = __shfl_down_sync(0xffffffffu, best_v[s], off);
            int   oi = __shfl_down_sync(0xffffffffu, best_i[s], off);
            if (ov > best_v[s] || (ov == best_v[s] && oi < best_i[s])) {
                best_v[s] = ov; best_i[s] = oi;
            }
        }
    }
    if ((lane & 3) == 0) {
        int q = lane >> 2;
        #pragma unroll
        for (int s = 0; s < 2; ++s) {
            s_best[rb + 8 * s + q] = best_i[s];
        }
    }
    __syncthreads();

    // ---- phase 3: exact fp32 loss for assigned center (4 threads/row) ----
    {
        int r = tid >> 2;        // 0..127
        int q = tid & 3;         // dim quarter
        float ri = s_ri[r];
        int   bi = s_best[r];
        const float4* fp = (const float4*)(features + (size_t)(row0 + r) * DDIM)
                         + 8 * q;
        const float4* cp = (const float4*)(centers + (size_t)bi * DDIM) + 8 * q;
        float ls = 0.0f;
        #pragma unroll
        for (int j = 0; j < 8; ++j) {
            float4 f = fp[j], c = cp[j];
            float dx = fmaf(f.x, ri, -c.x);
            float dy = fmaf(f.y, ri, -c.y);
            float dz = fmaf(f.z, ri, -c.z);
            float dw = fmaf(f.w, ri, -c.w);
            ls += dx * dx + dy * dy + dz * dz + dw * dw;
        }
        #pragma unroll
        for (int o = 16; o; o >>= 1) ls += __shfl_xor_sync(0xffffffffu, ls, o);
        if (lane == 0) spart[w] = ls;
    }
    __syncthreads();
    if (tid == 0) {
        float bs = 0.0f;
        #pragma unroll
        for (int i = 0; i < 16; ++i) bs += spart[i];
        atomicAdd(&g_sum, (double)bs);
    }
}

// ---------------------------------------------------------------------------
__global__ void finalize_kernel(float* out, int N) {
    out[0] = (float)(g_sum / (double)N);
}

extern "C" void kernel_launch(void* const* d_in, const int* in_sizes, int n_in,
                              void* d_out, int out_size) {
    const float* features = (const float*)d_in[0];
    const float* centers  = (const float*)d_in[1];
    int N = in_sizes[0] / DDIM;

    const int smem_bytes = 98304 + 1024 + 64 * 4;
    cudaFuncSetAttribute(cluster_main_kernel,
                         cudaFuncAttributeMaxDynamicSharedMemorySize, smem_bytes);

    prep_centers_kernel<<<KCENT, 128>>>(centers);
    cluster_main_kernel<<<N / MC, THREADS, smem_bytes>>>(features, centers, N);
    finalize_kernel<<<1, 1>>>((float*)d_out, N);
}

// round 9
// speedup vs baseline: 1.0393x; 1.0393x over previous
#include <cuda_runtime.h>
#include <cuda_fp16.h>
#include <math.h>
#include <stdint.h>

#define DDIM  128
#define MC    256          // rows per CTA
#define NB    128          // centers per B tile
#define NTILE 8            // K / NB
#define KCENT 1024
#define EPSF  1e-12f
#define THREADS 512

// ---------------- device scratch (no allocations allowed) -------------------
__device__ __half g_chf[KCENT * DDIM];   // normalized centers, fp16
__device__ double g_sum;

// ---------------- helpers ---------------------------------------------------
__device__ __forceinline__ uint32_t smem_u32(const void* p) {
    uint32_t a;
    asm("{ .reg .u64 t; cvta.to.shared.u64 t, %1; cvt.u32.u64 %0, t; }"
        : "=r"(a) : "l"(p));
    return a;
}
__device__ __forceinline__ void cpa16(uint32_t dst, const void* src) {
    asm volatile("cp.async.cg.shared.global [%0], [%1], 16;"
                 :: "r"(dst), "l"(src));
}
__device__ __forceinline__ void cpa_commit() {
    asm volatile("cp.async.commit_group;" ::: "memory");
}
__device__ __forceinline__ void cpa_wait0() {
    asm volatile("cp.async.wait_group 0;" ::: "memory");
}
__device__ __forceinline__ void cpa_wait1() {
    asm volatile("cp.async.wait_group 1;" ::: "memory");
}
__device__ __forceinline__ void ldsm_x4(uint32_t* r, uint32_t addr) {
    asm volatile("ldmatrix.sync.aligned.m8n8.x4.shared.b16 {%0,%1,%2,%3}, [%4];"
                 : "=r"(r[0]), "=r"(r[1]), "=r"(r[2]), "=r"(r[3]) : "r"(addr));
}
// f16 accumulate MMA: d = {2 x b32} holding 4 fp16
__device__ __forceinline__ void mma16816h(uint32_t* d, const uint32_t* a,
                                          const uint32_t* b) {
    asm volatile(
        "mma.sync.aligned.m16n8k16.row.col.f16.f16.f16.f16 "
        "{%0,%1}, {%2,%3,%4,%5}, {%6,%7}, {%0,%1};"
        : "+r"(d[0]), "+r"(d[1])
        : "r"(a[0]), "r"(a[1]), "r"(a[2]), "r"(a[3]), "r"(b[0]), "r"(b[1]));
}
__device__ __forceinline__ uint32_t pack_h2(float a, float b) {
    __half2 h = __floats2half2_rn(a, b);
    return *(uint32_t*)&h;
}
// row-major fp16 tile, 256B rows (16 x 16B chunks), XOR-8 swizzle
__device__ __forceinline__ uint32_t swz(uint32_t row, uint32_t chunk) {
    return row * 256u + ((chunk ^ (row & 7u)) << 4);
}

// ---------------------------------------------------------------------------
// Kernel A: normalize centers -> fp16 row-major; zero accumulator.
// ---------------------------------------------------------------------------
__global__ void prep_centers_kernel(const float* __restrict__ centers) {
    int k = blockIdx.x;
    int t = threadIdx.x;

    float v = centers[(size_t)k * DDIM + t];
    float s = v * v;
    #pragma unroll
    for (int o = 16; o; o >>= 1) s += __shfl_xor_sync(0xffffffffu, s, o);

    __shared__ float ws[4];
    __shared__ float n2s;
    if ((t & 31) == 0) ws[t >> 5] = s;
    __syncthreads();
    if (t == 0) {
        n2s = ws[0] + ws[1] + ws[2] + ws[3];
        if (k == 0) g_sum = 0.0;
    }
    __syncthreads();

    float ri = 1.0f / fmaxf(sqrtf(n2s), EPSF);
    g_chf[(size_t)k * DDIM + t] = __float2half(v * ri);
}

// ---------------------------------------------------------------------------
// Kernel B: fp16 mma.sync GEMM (sims, f16 acc) + fused argmax + exact loss.
// 512 threads, 256 rows/CTA. Warp tile 32(m) x 64(n); warps 8(m) x 2(n).
// B: 3 buffers, 2-deep cp.async prefetch, one barrier per tile.
// ---------------------------------------------------------------------------
__global__ void __launch_bounds__(THREADS, 1) cluster_main_kernel(
    const float* __restrict__ features,
    const float* __restrict__ centers, int N)
{
    extern __shared__ char dsm[];
    // layout: A (64KB) | B[3] (96KB) | s_ri (1KB) | s_best (1KB) | spart
    const uint32_t Ab = smem_u32(dsm);
    const uint32_t Bb = Ab + 65536u;
    float* s_ri   = (float*)(dsm + 163840);
    int*   s_best = (int*)  (dsm + 163840 + 1024);
    float* spart  = (float*)(dsm + 163840 + 2048);

    const int tid  = threadIdx.x;
    const int lane = tid & 31;
    const int w    = tid >> 5;          // 0..15
    const int row0 = blockIdx.x * MC;

    // ---- kick off B tiles 0 and 1 (two commit groups) ----
    #pragma unroll
    for (int t0 = 0; t0 < 2; ++t0) {
        const char* src = (const char*)(g_chf + (size_t)t0 * NB * DDIM);
        uint32_t dst = Bb + (uint32_t)t0 * 32768u;
        #pragma unroll
        for (int j = tid; j < 2048; j += THREADS) {
            int n = j >> 4, c = j & 15;
            cpa16(dst + swz(n, c), src + n * 256 + c * 16);
        }
        cpa_commit();
    }

    // ---- phase 1: load 256 feature rows, normalize, fp16 -> smem A ----
    #pragma unroll 4
    for (int i = 0; i < 16; ++i) {
        int r = 16 * w + i;
        float4 v = *(const float4*)(features + (size_t)(row0 + r) * DDIM
                                    + 4 * lane);
        float s = v.x * v.x + v.y * v.y + v.z * v.z + v.w * v.w;
        #pragma unroll
        for (int o = 16; o; o >>= 1) s += __shfl_xor_sync(0xffffffffu, s, o);
        float ri = 1.0f / fmaxf(sqrtf(s), EPSF);
        if (lane == 0) s_ri[r] = ri;
        uint32_t p0 = pack_h2(v.x * ri, v.y * ri);
        uint32_t p1 = pack_h2(v.z * ri, v.w * ri);
        uint32_t addr = Ab + swz(r, lane >> 1) + (lane & 1) * 8;
        asm volatile("st.shared.v2.b32 [%0], {%1,%2};"
                     :: "r"(addr), "r"(p0), "r"(p1));
    }

    // ---- warp tiling ----
    const int wm = w & 7, wn = w >> 3;
    const int rb = 32 * wm;          // warp row base
    const int nb0 = 64 * wn;         // warp col base within tile

    float best_v[4];
    int   best_i[4];
    #pragma unroll
    for (int s = 0; s < 4; ++s) { best_v[s] = -INFINITY; best_i[s] = 0; }

    #pragma unroll 1
    for (int t = 0; t < NTILE; ++t) {
        if (t < NTILE - 1) cpa_wait1(); else cpa_wait0();
        __syncthreads();   // tile t data visible; buf[(t+2)%3] free
        const uint32_t Bt = Bb + (uint32_t)(t % 3) * 32768u;

        if (t + 2 < NTILE) {   // prefetch tile t+2 (2-deep)
            const char* src = (const char*)(g_chf + (size_t)(t + 2) * NB * DDIM);
            uint32_t dst = Bb + (uint32_t)((t + 2) % 3) * 32768u;
            #pragma unroll
            for (int j = tid; j < 2048; j += THREADS) {
                int n = j >> 4, c = j & 15;
                cpa16(dst + swz(n, c), src + n * 256 + c * 16);
            }
            cpa_commit();
        }

        uint32_t acc[2][8][2];
        #pragma unroll
        for (int a = 0; a < 2; ++a)
            #pragma unroll
            for (int b = 0; b < 8; ++b) { acc[a][b][0] = 0u; acc[a][b][1] = 0u; }

        #pragma unroll
        for (int ks = 0; ks < 8; ++ks) {
            uint32_t a0[4], a1[4];
            {
                int row = rb + (lane & 15);
                int ch  = 2 * ks + (lane >> 4);
                ldsm_x4(a0, Ab + swz(row, ch));
                ldsm_x4(a1, Ab + swz(row + 16, ch));
            }
            uint32_t bfr[8][2];
            #pragma unroll
            for (int g = 0; g < 4; ++g) {
                int n  = nb0 + 16 * g + (lane & 7) + ((lane >> 4) << 3);
                int ch = 2 * ks + ((lane >> 3) & 1);
                uint32_t r4[4];
                ldsm_x4(r4, Bt + swz(n, ch));
                bfr[2 * g][0] = r4[0]; bfr[2 * g][1] = r4[1];
                bfr[2 * g + 1][0] = r4[2]; bfr[2 * g + 1][1] = r4[3];
            }
            #pragma unroll
            for (int nt = 0; nt < 8; ++nt) {
                mma16816h(acc[0][nt], a0, bfr[nt]);
                mma16816h(acc[1][nt], a1, bfr[nt]);
            }
        }

        // fold argmax: slot s = 2*mt + rh; rows rb + 16*mt + (lane>>2) + 8*rh
        const int kbase = t * NB + nb0 + 2 * (lane & 3);
        #pragma unroll
        for (int mt = 0; mt < 2; ++mt) {
            #pragma unroll
            for (int rh = 0; rh < 2; ++rh) {
                int s = 2 * mt + rh;
                #pragma unroll
                for (int nt = 0; nt < 8; ++nt) {
                    __half2 h = *(__half2*)&acc[mt][nt][rh];
                    float v0 = __low2float(h);
                    float v1 = __high2float(h);
                    int   i0 = kbase + 8 * nt;
                    if (v0 > best_v[s]) { best_v[s] = v0; best_i[s] = i0; }
                    if (v1 > best_v[s]) { best_v[s] = v1; best_i[s] = i0 + 1; }
                }
            }
        }
    }

    // ---- reduce argmax over the 4 lanes of each quad ----
    #pragma unroll
    for (int off = 1; off < 4; off <<= 1) {
        #pragma unroll
        for (int s = 0; s < 4; ++s) {
            float ov = __shfl_down_sync(0xffffffffu, best_v[s], off);
            int   oi = __shfl_down_sync(0xffffffffu, best_i[s], off);
            if (ov > best_v[s] || (ov == best_v[s] && oi < best_i[s])) {
                best_v[s] = ov; best_i[s] = oi;
            }
        }
    }
    if ((lane & 3) == 0) {
        int q = lane >> 2;
        #pragma unroll
        for (int s = 0; s < 4; ++s) {
            int mt = s >> 1, rh = s & 1;
            s_best[rb + 16 * mt + 8 * rh + q] = best_i[s];
        }
    }
    __syncthreads();

    // ---- phase 3: exact fp32 loss for assigned center (2 threads/row) ----
    {
        int r = tid >> 1;        // 0..255
        int hq = tid & 1;        // dim half
        float ri = s_ri[r];
        int   bi = s_best[r];
        const float4* fp = (const float4*)(features + (size_t)(row0 + r) * DDIM)
                         + 16 * hq;
        const float4* cp = (const float4*)(centers + (size_t)bi * DDIM) + 16 * hq;
        float ls = 0.0f;
        #pragma unroll
        for (int j = 0; j < 16; ++j) {
            float4 f = fp[j], c = cp[j];
            float dx = fmaf(f.x, ri, -c.x);
            float dy = fmaf(f.y, ri, -c.y);
            float dz = fmaf(f.z, ri, -c.z);
            float dw = fmaf(f.w, ri, -c.w);
            ls += dx * dx + dy * dy + dz * dz + dw * dw;
        }
        #pragma unroll
        for (int o = 16; o; o >>= 1) ls += __shfl_xor_sync(0xffffffffu, ls, o);
        if (lane == 0) spart[w] = ls;
    }
    __syncthreads();
    if (tid == 0) {
        float bs = 0.0f;
        #pragma unroll
        for (int i = 0; i < 16; ++i) bs += spart[i];
        atomicAdd(&g_sum, (double)bs);
    }
}

// ---------------------------------------------------------------------------
__global__ void finalize_kernel(float* out, int N) {
    out[0] = (float)(g_sum / (double)N);
}

extern "C" void kernel_launch(void* const* d_in, const int* in_sizes, int n_in,
                              void* d_out, int out_size) {
    const float* features = (const float*)d_in[0];
    const float* centers  = (const float*)d_in[1];
    int N = in_sizes[0] / DDIM;

    const int smem_bytes = 163840 + 2048 + 64 * 4;
    cudaFuncSetAttribute(cluster_main_kernel,
                         cudaFuncAttributeMaxDynamicSharedMemorySize, smem_bytes);

    prep_centers_kernel<<<KCENT, 128>>>(centers);
    cluster_main_kernel<<<N / MC, THREADS, smem_bytes>>>(features, centers, N);
    finalize_kernel<<<1, 1>>>((float*)d_out, N);
}

// round 11
// speedup vs baseline: 1.0935x; 1.0521x over previous
#include <cuda_runtime.h>
#include <cuda_bf16.h>
#include <math.h>
#include <stdint.h>

#define DDIM  128
#define MC    128          // rows per CTA
#define NB    128          // centers per B tile
#define NTILE 8            // K / NB
#define KCENT 1024
#define EPSF  1e-12f
#define THREADS 256

// ---------------- device scratch (no allocations allowed) -------------------
__device__ __nv_bfloat16 g_cbf[KCENT * DDIM];   // normalized centers, bf16
__device__ double g_sum;

// ---------------- helpers ---------------------------------------------------
__device__ __forceinline__ uint32_t smem_u32(const void* p) {
    uint32_t a;
    asm("{ .reg .u64 t; cvta.to.shared.u64 t, %1; cvt.u32.u64 %0, t; }"
        : "=r"(a) : "l"(p));
    return a;
}
__device__ __forceinline__ void cpa16(uint32_t dst, const void* src) {
    asm volatile("cp.async.cg.shared.global [%0], [%1], 16;"
                 :: "r"(dst), "l"(src));
}
__device__ __forceinline__ void cpa_commit() {
    asm volatile("cp.async.commit_group;" ::: "memory");
}
__device__ __forceinline__ void cpa_wait0() {
    asm volatile("cp.async.wait_group 0;" ::: "memory");
}
__device__ __forceinline__ void ldsm_x4(uint32_t* r, uint32_t addr) {
    asm volatile("ldmatrix.sync.aligned.m8n8.x4.shared.b16 {%0,%1,%2,%3}, [%4];"
                 : "=r"(r[0]), "=r"(r[1]), "=r"(r[2]), "=r"(r[3]) : "r"(addr));
}
__device__ __forceinline__ void mma16816(float* d, const uint32_t* a,
                                         const uint32_t* b) {
    asm volatile(
        "mma.sync.aligned.m16n8k16.row.col.f32.bf16.bf16.f32 "
        "{%0,%1,%2,%3}, {%4,%5,%6,%7}, {%8,%9}, {%0,%1,%2,%3};"
        : "+f"(d[0]), "+f"(d[1]), "+f"(d[2]), "+f"(d[3])
        : "r"(a[0]), "r"(a[1]), "r"(a[2]), "r"(a[3]), "r"(b[0]), "r"(b[1]));
}
__device__ __forceinline__ uint32_t pack_bf2(float a, float b) {
    __nv_bfloat16 ha = __float2bfloat16(a);
    __nv_bfloat16 hb = __float2bfloat16(b);
    return (uint32_t)__bfloat16_as_ushort(ha)
         | ((uint32_t)__bfloat16_as_ushort(hb) << 16);
}
// row-major bf16 tile, 256B rows (16 x 16B chunks), XOR-8 swizzle
__device__ __forceinline__ uint32_t swz(uint32_t row, uint32_t chunk) {
    return row * 256u + ((chunk ^ (row & 7u)) << 4);
}

// ---------------------------------------------------------------------------
// Kernel A: normalize centers -> bf16 row-major; zero accumulator.
// ---------------------------------------------------------------------------
__global__ void prep_centers_kernel(const float* __restrict__ centers) {
    int k = blockIdx.x;
    int t = threadIdx.x;

    float v = centers[(size_t)k * DDIM + t];
    float s = v * v;
    #pragma unroll
    for (int o = 16; o; o >>= 1) s += __shfl_xor_sync(0xffffffffu, s, o);

    __shared__ float ws[4];
    __shared__ float n2s;
    if ((t & 31) == 0) ws[t >> 5] = s;
    __syncthreads();
    if (t == 0) {
        n2s = ws[0] + ws[1] + ws[2] + ws[3];
        if (k == 0) g_sum = 0.0;
    }
    __syncthreads();

    float ri = 1.0f / fmaxf(sqrtf(n2s), EPSF);
    g_cbf[(size_t)k * DDIM + t] = __float2bfloat16(v * ri);
}

// ---------------------------------------------------------------------------
// Kernel B: bf16 mma.sync GEMM (sims) + fused argmax + exact fp32 loss.
// 256 threads, 128 rows/CTA, 2 CTAs/SM. Warp tile 32(m) x 64(n); warps 4x2.
// Each n-warp half stores its own (best_v, best_i); phase 3 merges them.
// ---------------------------------------------------------------------------
__global__ void __launch_bounds__(THREADS, 2) cluster_main_kernel(
    const float* __restrict__ features,
    const float* __restrict__ centers, int N)
{
    extern __shared__ char dsm[];
    // layout: A (32KB) | B[2] (64KB) | s_ri | s_bv[2][128] | s_bi[2][128] | spart
    const uint32_t Ab = smem_u32(dsm);
    const uint32_t Bb = Ab + 32768u;
    float* s_ri = (float*)(dsm + 98304);                 // 512 B
    float* s_bv = (float*)(dsm + 98304 + 512);           // 1024 B (2 x 128)
    int*   s_bi = (int*)  (dsm + 98304 + 512 + 1024);    // 1024 B (2 x 128)
    float* spart = (float*)(dsm + 98304 + 512 + 2048);   // 32 B

    const int tid  = threadIdx.x;
    const int lane = tid & 31;
    const int w    = tid >> 5;          // 0..7
    const int row0 = blockIdx.x * MC;

    // ---- kick off B tile 0 load ----
    {
        const char* src = (const char*)g_cbf;
        #pragma unroll
        for (int j = tid; j < 2048; j += THREADS) {
            int n = j >> 4, c = j & 15;
            cpa16(Bb + swz(n, c), src + n * 256 + c * 16);
        }
        cpa_commit();
    }

    // ---- phase 1: load 128 feature rows, normalize, bf16 -> smem A ----
    #pragma unroll 4
    for (int i = 0; i < 16; ++i) {
        int r = 16 * w + i;
        float4 v = *(const float4*)(features + (size_t)(row0 + r) * DDIM
                                    + 4 * lane);
        float s = v.x * v.x + v.y * v.y + v.z * v.z + v.w * v.w;
        #pragma unroll
        for (int o = 16; o; o >>= 1) s += __shfl_xor_sync(0xffffffffu, s, o);
        float ri = 1.0f / fmaxf(sqrtf(s), EPSF);
        if (lane == 0) s_ri[r] = ri;
        uint32_t p0 = pack_bf2(v.x * ri, v.y * ri);
        uint32_t p1 = pack_bf2(v.z * ri, v.w * ri);
        uint32_t addr = Ab + swz(r, lane >> 1) + (lane & 1) * 8;
        asm volatile("st.shared.v2.b32 [%0], {%1,%2};"
                     :: "r"(addr), "r"(p0), "r"(p1));
    }
    __syncthreads();

    // ---- warp tiling: 4(m) x 2(n), warp tile 32 x 64 ----
    const int wm = w & 3, wn = w >> 2;
    const int rb = 32 * wm;          // warp row base
    const int nb0 = 64 * wn;         // warp col base within tile

    float best_v[4];
    int   best_i[4];
    #pragma unroll
    for (int s = 0; s < 4; ++s) { best_v[s] = -INFINITY; best_i[s] = 0; }

    #pragma unroll 1
    for (int t = 0; t < NTILE; ++t) {
        cpa_wait0();
        __syncthreads();
        const uint32_t Bt = Bb + (uint32_t)(t & 1) * 32768u;

        if (t < NTILE - 1) {   // prefetch next tile into other buffer
            const char* src = (const char*)(g_cbf + (size_t)(t + 1) * NB * DDIM);
            uint32_t dst = Bb + (uint32_t)((t + 1) & 1) * 32768u;
            #pragma unroll
            for (int j = tid; j < 2048; j += THREADS) {
                int n = j >> 4, c = j & 15;
                cpa16(dst + swz(n, c), src + n * 256 + c * 16);
            }
            cpa_commit();
        }

        float acc[2][8][4];
        #pragma unroll
        for (int a = 0; a < 2; ++a)
            #pragma unroll
            for (int b = 0; b < 8; ++b)
                #pragma unroll
                for (int e = 0; e < 4; ++e) acc[a][b][e] = 0.0f;

        #pragma unroll
        for (int ks = 0; ks < 8; ++ks) {
            uint32_t a0[4], a1[4];
            {
                int row = rb + (lane & 15);
                int ch  = 2 * ks + (lane >> 4);
                ldsm_x4(a0, Ab + swz(row, ch));
                ldsm_x4(a1, Ab + swz(row + 16, ch));
            }
            uint32_t bfr[8][2];
            #pragma unroll
            for (int g = 0; g < 4; ++g) {
                int n  = nb0 + 16 * g + (lane & 7) + ((lane >> 4) << 3);
                int ch = 2 * ks + ((lane >> 3) & 1);
                uint32_t r4[4];
                ldsm_x4(r4, Bt + swz(n, ch));
                bfr[2 * g][0] = r4[0]; bfr[2 * g][1] = r4[1];
                bfr[2 * g + 1][0] = r4[2]; bfr[2 * g + 1][1] = r4[3];
            }
            #pragma unroll
            for (int nt = 0; nt < 8; ++nt) {
                mma16816(acc[0][nt], a0, bfr[nt]);
                mma16816(acc[1][nt], a1, bfr[nt]);
            }
        }
        __syncthreads();   // all warps done reading Bt before it is refilled

        // fold argmax: slot s = 2*mt + rh; rows rb + 16*mt + (lane>>2) + 8*rh
        const int kbase = t * NB + nb0 + 2 * (lane & 3);
        #pragma unroll
        for (int mt = 0; mt < 2; ++mt) {
            #pragma unroll
            for (int rh = 0; rh < 2; ++rh) {
                int s = 2 * mt + rh;
                #pragma unroll
                for (int nt = 0; nt < 8; ++nt) {
                    float v0 = acc[mt][nt][2 * rh];
                    float v1 = acc[mt][nt][2 * rh + 1];
                    int   i0 = kbase + 8 * nt;
                    if (v0 > best_v[s]) { best_v[s] = v0; best_i[s] = i0; }
                    if (v1 > best_v[s]) { best_v[s] = v1; best_i[s] = i0 + 1; }
                }
            }
        }
    }

    // ---- reduce argmax over the 4 lanes of each quad ----
    #pragma unroll
    for (int off = 1; off < 4; off <<= 1) {
        #pragma unroll
        for (int s = 0; s < 4; ++s) {
            float ov = __shfl_down_sync(0xffffffffu, best_v[s], off);
            int   oi = __shfl_down_sync(0xffffffffu, best_i[s], off);
            if (ov > best_v[s] || (ov == best_v[s] && oi < best_i[s])) {
                best_v[s] = ov; best_i[s] = oi;
            }
        }
    }
    // each n-warp half writes its OWN slot (no cross-half race)
    if ((lane & 3) == 0) {
        int q = lane >> 2;
        #pragma unroll
        for (int s = 0; s < 4; ++s) {
            int mt = s >> 1, rh = s & 1;
            int r = rb + 16 * mt + 8 * rh + q;
            s_bv[wn * MC + r] = best_v[s];
            s_bi[wn * MC + r] = best_i[s];
        }
    }
    __syncthreads();

    // ---- phase 3: merge halves + exact fp32 loss (2 threads/row) ----
    {
        int r = tid >> 1;        // 0..127
        int hq = tid & 1;        // dim half
        float v0 = s_bv[r],      v1 = s_bv[MC + r];
        int   i0 = s_bi[r],      i1 = s_bi[MC + r];
        int bi = (v1 > v0 || (v1 == v0 && i1 < i0)) ? i1 : i0;
        float ri = s_ri[r];
        const float4* fp = (const float4*)(features + (size_t)(row0 + r) * DDIM)
                         + 16 * hq;
        const float4* cp = (const float4*)(centers + (size_t)bi * DDIM) + 16 * hq;
        float ls = 0.0f;
        #pragma unroll
        for (int j = 0; j < 16; ++j) {
            float4 f = fp[j], c = cp[j];
            float dx = fmaf(f.x, ri, -c.x);
            float dy = fmaf(f.y, ri, -c.y);
            float dz = fmaf(f.z, ri, -c.z);
            float dw = fmaf(f.w, ri, -c.w);
            ls += dx * dx + dy * dy + dz * dz + dw * dw;
        }
        #pragma unroll
        for (int o = 16; o; o >>= 1) ls += __shfl_xor_sync(0xffffffffu, ls, o);
        if (lane == 0) spart[w] = ls;
    }
    __syncthreads();
    if (tid == 0) {
        float bs = 0.0f;
        #pragma unroll
        for (int i = 0; i < 8; ++i) bs += spart[i];
        atomicAdd(&g_sum, (double)bs);
    }
}

// ---------------------------------------------------------------------------
__global__ void finalize_kernel(float* out, int N) {
    out[0] = (float)(g_sum / (double)N);
}

extern "C" void kernel_launch(void* const* d_in, const int* in_sizes, int n_in,
                              void* d_out, int out_size) {
    const float* features = (const float*)d_in[0];
    const float* centers  = (const float*)d_in[1];
    int N = in_sizes[0] / DDIM;

    const int smem_bytes = 98304 + 512 + 2048 + 32;
    cudaFuncSetAttribute(cluster_main_kernel,
                         cudaFuncAttributeMaxDynamicSharedMemorySize, smem_bytes);

    prep_centers_kernel<<<KCENT, 128>>>(centers);
    cluster_main_kernel<<<N / MC, THREADS, smem_bytes>>>(features, centers, N);
    finalize_kernel<<<1, 1>>>((float*)d_out, N);
}